// round 3
// baseline (speedup 1.0000x reference)
#include <cuda_runtime.h>
#include <cuda_bf16.h>
#include <cstdint>

// CausalConv1d as grouped GEMM on mma.sync bf16 (3-term hi/lo split emulating fp32).
// B=4, L=4096, D=2048, K=4, G=8.
// Per (b,g): C[4096,256] = A[4096,1024] x B[1024,256],
//   A[l, (ks,cin)] = x[b, l+ks-3, g*256+cin] (causal zero-pad), B[(ks,cin), n] = w[ks, cin, g*256+n].
// tcgen05 unavailable (harness compiles via compute_103 virtual arch) -> Ampere-style HMMA kernel.

#define B_ 4
#define L_ 4096
#define D_ 2048
#define CPG 256
#define TM 128
#define TN 128
#define NSTAGES 16     // 4 channel blocks x 4 taps
#define NTHREADS 256

// __device__ scratch: pre-split bf16 hi/lo copies of x and w.
__device__ __nv_bfloat16 g_xh[B_ * L_ * D_];
__device__ __nv_bfloat16 g_xl[B_ * L_ * D_];
__device__ __nv_bfloat16 g_wh[4 * 256 * D_];
__device__ __nv_bfloat16 g_wl[4 * 256 * D_];

// smem layout (bytes):
//  A: 2 bufs x [2 (h/l)][132 rows][128B]  (rows = 131 used: l0-3 .. l0+127)
//  B: 2 bufs x [2 (h/l)][64 rows][256B]
#define A_HL 16896          // 132*128
#define A_BUF 33792         // 2*A_HL
#define OFF_B 67584         // 2*A_BUF
#define B_HL 16384          // 64*256
#define B_BUF 32768
#define SMEM_TOTAL (OFF_B + 2 * B_BUF)   // 133120

__device__ __forceinline__ uint32_t s2u(const void* p) {
    uint32_t a;
    asm("{ .reg .u64 t; cvta.to.shared.u64 t, %1; cvt.u32.u64 %0, t; }" : "=r"(a) : "l"(p));
    return a;
}

__device__ __forceinline__ void cp16(uint32_t dst, const void* src, uint32_t bytes) {
    asm volatile("cp.async.cg.shared.global [%0], [%1], 16, %2;"
                 :: "r"(dst), "l"(src), "r"(bytes));
}

#define LDSM4(r0, r1, r2, r3, a)                                                   \
    asm volatile("ldmatrix.sync.aligned.m8n8.x4.shared.b16 {%0,%1,%2,%3}, [%4];"   \
                 : "=r"(r0), "=r"(r1), "=r"(r2), "=r"(r3) : "r"(a))

#define LDSM4T(r0, r1, r2, r3, a)                                                       \
    asm volatile("ldmatrix.sync.aligned.m8n8.x4.trans.shared.b16 {%0,%1,%2,%3}, [%4];"  \
                 : "=r"(r0), "=r"(r1), "=r"(r2), "=r"(r3) : "r"(a))

#define MMA(d, a0, a1, a2, a3, b0, b1)                                             \
    asm volatile("mma.sync.aligned.m16n8k16.row.col.f32.bf16.bf16.f32 "            \
                 "{%0,%1,%2,%3},{%4,%5,%6,%7},{%8,%9},{%0,%1,%2,%3};"              \
                 : "+f"((d)[0]), "+f"((d)[1]), "+f"((d)[2]), "+f"((d)[3])          \
                 : "r"(a0), "r"(a1), "r"(a2), "r"(a3), "r"(b0), "r"(b1))

// Split fp32 pair -> packed bf16x2 hi and lo.
__device__ __forceinline__ void cvt_hl(float a, float b, uint32_t& hv, uint32_t& lv) {
    __nv_bfloat162 h = __floats2bfloat162_rn(a, b);
    uint32_t hb = *reinterpret_cast<uint32_t*>(&h);
    float ra = a - __uint_as_float(hb << 16);
    float rb = b - __uint_as_float(hb & 0xFFFF0000u);
    __nv_bfloat162 l = __floats2bfloat162_rn(ra, rb);
    hv = hb;
    lv = *reinterpret_cast<uint32_t*>(&l);
}

__global__ void __launch_bounds__(NTHREADS) cvt_x_kernel(const float* __restrict__ x) {
    size_t i = (size_t)blockIdx.x * NTHREADS + threadIdx.x;   // float4 index
    float4 v = reinterpret_cast<const float4*>(x)[i];
    uint32_t h0, l0, h1, l1;
    cvt_hl(v.x, v.y, h0, l0);
    cvt_hl(v.z, v.w, h1, l1);
    reinterpret_cast<uint2*>(g_xh)[i] = make_uint2(h0, h1);
    reinterpret_cast<uint2*>(g_xl)[i] = make_uint2(l0, l1);
}

__global__ void __launch_bounds__(NTHREADS) cvt_w_kernel(const float* __restrict__ w) {
    size_t i = (size_t)blockIdx.x * NTHREADS + threadIdx.x;
    float4 v = reinterpret_cast<const float4*>(w)[i];
    uint32_t h0, l0, h1, l1;
    cvt_hl(v.x, v.y, h0, l0);
    cvt_hl(v.z, v.w, h1, l1);
    reinterpret_cast<uint2*>(g_wh)[i] = make_uint2(h0, h1);
    reinterpret_cast<uint2*>(g_wl)[i] = make_uint2(l0, l1);
}

// ---- loaders (all 256 threads) ----
// A block: 131 rows (l0-3 .. l0+127) x 64 ch, hi+lo. chunks: 2*131*8 = 2096.
__device__ __forceinline__ void load_A(uint32_t smem_base, int abuf, int b, int l0,
                                       int gch0 /* gcol + cbase */) {
    const uint32_t base = smem_base + abuf * A_BUF;
    for (int idx = threadIdx.x; idx < 2096; idx += NTHREADS) {
        int hl  = idx >= 1048;
        int rem = hl ? idx - 1048 : idx;
        int row = rem >> 3;
        int c   = rem & 7;
        int l   = l0 - 3 + row;
        uint32_t bytes = (l >= 0) ? 16u : 0u;   // src-size 0 -> zero-fill (causal pad)
        int lc = l >= 0 ? l : 0;
        const __nv_bfloat16* src = (hl ? g_xl : g_xh) + ((size_t)(b * L_ + lc) * D_ + gch0 + c * 8);
        uint32_t dst = base + hl * A_HL + row * 128 + (((uint32_t)c ^ (row & 7)) << 4);
        cp16(dst, src, bytes);
    }
}

// B stage: 64 k-rows (cin) x 128 n, hi+lo. chunks: 2*64*16 = 2048.
__device__ __forceinline__ void load_B(uint32_t smem_base, int bbuf, int ks, int cbase,
                                       int ncol0 /* gcol + nt*128 */) {
    const uint32_t base = smem_base + OFF_B + bbuf * B_BUF;
    for (int idx = threadIdx.x; idx < 2048; idx += NTHREADS) {
        int hl  = idx >> 10;
        int rem = idx & 1023;
        int row = rem >> 4;
        int c   = rem & 15;
        const __nv_bfloat16* src =
            (hl ? g_wl : g_wh) + ((size_t)(ks * 256 + cbase + row) * D_ + ncol0 + c * 8);
        uint32_t dst = base + hl * B_HL + row * 256 + (((uint32_t)c ^ (row & 7)) << 4);
        cp16(dst, src, 16u);
    }
}

__global__ void __launch_bounds__(NTHREADS, 1)
cc1d_mma_kernel(float* __restrict__ out) {
    extern __shared__ char smem[];
    const uint32_t smem_base = s2u(smem);
    const int tid = threadIdx.x;
    const int wid = tid >> 5;
    const int lid = tid & 31;
    const int wm = wid & 3;      // warp row: 32 rows
    const int wn = wid >> 2;     // warp col: 64 cols

    const int bid = blockIdx.x;
    const int nt = bid & 1;
    const int lt = (bid >> 1) & 31;
    const int g  = (bid >> 6) & 7;
    const int b  = bid >> 9;
    const int l0 = lt * TM;
    const int gcol = g * CPG;
    const int ncol0 = gcol + nt * TN;

    // ---- prologue ----
    load_A(smem_base, 0, b, l0, gcol + 0);
    load_B(smem_base, 0, /*ks=*/0, /*cbase=*/0, ncol0);
    asm volatile("cp.async.commit_group;");
    load_B(smem_base, 1, /*ks=*/1, /*cbase=*/0, ncol0);
    asm volatile("cp.async.commit_group;");

    float acc[2][8][4];
#pragma unroll
    for (int u = 0; u < 2; ++u)
#pragma unroll
        for (int j = 0; j < 8; ++j)
#pragma unroll
            for (int q = 0; q < 4; ++q) acc[u][j][q] = 0.f;

    for (int s = 0; s < NSTAGES; ++s) {
        const int ks = s & 3;
        const int abuf = (s >> 2) & 1;
        const int bbuf = s & 1;

        if (s == NSTAGES - 1) asm volatile("cp.async.wait_group 0;");
        else                  asm volatile("cp.async.wait_group 1;");
        __syncthreads();

        const uint32_t sA = smem_base + abuf * A_BUF;
        const uint32_t sB = smem_base + OFF_B + bbuf * B_BUF;

#pragma unroll
        for (int t = 0; t < 4; ++t) {
            uint32_t ah[2][4], al[2][4];
#pragma unroll
            for (int u = 0; u < 2; ++u) {
                int row = wm * 32 + u * 16 + (lid & 15) + ks;
                int lc  = t * 2 + (lid >> 4);
                uint32_t addr = sA + row * 128 + (((uint32_t)lc ^ (row & 7)) << 4);
                LDSM4(ah[u][0], ah[u][1], ah[u][2], ah[u][3], addr);
                LDSM4(al[u][0], al[u][1], al[u][2], al[u][3], addr + A_HL);
            }
            uint32_t bh[4][4], bl[4][4];
#pragma unroll
            for (int j2 = 0; j2 < 4; ++j2) {
                int row = t * 16 + (lid & 15);
                int lc  = wn * 8 + j2 * 2 + (lid >> 4);
                uint32_t addr = sB + row * 256 + (((uint32_t)lc ^ (row & 7)) << 4);
                LDSM4T(bh[j2][0], bh[j2][1], bh[j2][2], bh[j2][3], addr);
                LDSM4T(bl[j2][0], bl[j2][1], bl[j2][2], bl[j2][3], addr + B_HL);
            }
#pragma unroll
            for (int u = 0; u < 2; ++u)
#pragma unroll
                for (int j = 0; j < 8; ++j) {
                    int j2 = j >> 1, o = (j & 1) * 2;
                    MMA(acc[u][j], ah[u][0], ah[u][1], ah[u][2], ah[u][3],
                        bh[j2][o], bh[j2][o + 1]);
                    MMA(acc[u][j], al[u][0], al[u][1], al[u][2], al[u][3],
                        bh[j2][o], bh[j2][o + 1]);
                    MMA(acc[u][j], ah[u][0], ah[u][1], ah[u][2], ah[u][3],
                        bl[j2][o], bl[j2][o + 1]);
                }
        }

        if (s < NSTAGES - 2) {
            __syncthreads();   // all warps done with buffers about to be overwritten
            const int s2 = s + 2;
            if ((s2 & 3) == 0)
                load_A(smem_base, (s2 >> 2) & 1, b, l0, gcol + (s2 >> 2) * 64);
            load_B(smem_base, s2 & 1, s2 & 3, (s2 >> 2) * 64, ncol0);
            asm volatile("cp.async.commit_group;");
        }
    }

    // ---- epilogue: acc regs -> out ----
#pragma unroll
    for (int u = 0; u < 2; ++u)
#pragma unroll
        for (int j = 0; j < 8; ++j) {
            int m0 = wm * 32 + u * 16 + (lid >> 2);
            int n  = wn * 64 + j * 8 + (lid & 3) * 2;
            float* p = out + (size_t)(b * L_ + l0 + m0) * D_ + ncol0 + n;
            *reinterpret_cast<float2*>(p) = make_float2(acc[u][j][0], acc[u][j][1]);
            *reinterpret_cast<float2*>(p + 8 * D_) = make_float2(acc[u][j][2], acc[u][j][3]);
        }
}

extern "C" void kernel_launch(void* const* d_in, const int* in_sizes, int n_in,
                              void* d_out, int out_size) {
    const float* x = (const float*)d_in[0];   // [4, 4096, 2048] fp32
    const float* w = (const float*)d_in[1];   // [4, 256, 2048] fp32
    float* out = (float*)d_out;               // [4, 4096, 2048] fp32

    // pre-split fp32 -> bf16 hi/lo
    cvt_x_kernel<<<(B_ * L_ * D_ / 4) / NTHREADS, NTHREADS>>>(x);
    cvt_w_kernel<<<(4 * 256 * D_ / 4) / NTHREADS, NTHREADS>>>(w);

    cudaFuncSetAttribute(cc1d_mma_kernel, cudaFuncAttributeMaxDynamicSharedMemorySize, SMEM_TOTAL);
    // 2048 CTAs = 4 b x 8 g x 32 l-tiles x 2 n-tiles
    cc1d_mma_kernel<<<B_ * 8 * 32 * 2, NTHREADS, SMEM_TOTAL>>>(out);
}